// round 13
// baseline (speedup 1.0000x reference)
#include <cuda_runtime.h>
#include <cuda_bf16.h>
#include <cstdint>
#include <math.h>

#define N_NODESC 100000
#define N_EDGESC 400000
#define N_GRAPHSC 5000
#define F_INC 64
#define HC 128

// ---------------------------------------------------------------------------
// Scratch
// ---------------------------------------------------------------------------
__device__ __align__(16) float g_h   [(size_t)N_NODESC * HC];
__device__ __align__(16) float g_hs  [(size_t)N_NODESC * HC];
__device__ __align__(16) float g_as  [N_NODESC];
__device__ __align__(16) float g_ad  [N_NODESC];
__device__ __align__(16) float g_pooled[(size_t)N_GRAPHSC * HC];
__device__ __align__(16) float g_adg [N_GRAPHSC];
__device__ __align__(16) float g_wv  [HC];
// pre-split, pre-TRANSPOSED bf16 weights, layout [col][K]
#define WS_TOTAL (576 * 128)
#define WOFF_W1 0
#define WOFF_G(i) (8192 + (i) * 16384)
#define WOFF_M 57344
__device__ __align__(16) __nv_bfloat16 g_wbh[WS_TOTAL];
__device__ __align__(16) __nv_bfloat16 g_wbl[WS_TOTAL];
// CSR by destination
#define SCB 512
#define NSB ((N_NODESC + SCB - 1) / SCB)
__device__ int g_cnt   [N_NODESC];
__device__ int g_off   [N_NODESC + 1];
__device__ int g_cursor[N_NODESC];
__device__ int g_csrsrc[N_EDGESC];
__device__ int g_bsum  [NSB];
__device__ int g_boff  [NSB];
__device__ int g_gstart[N_GRAPHSC + 1];
__device__ int g_i64flag[2];

// ---------------------------------------------------------------------------
// dtype detection (int64 vs int32 indices)
// ---------------------------------------------------------------------------
__global__ void detect_kernel(const void* ei, const void* batch)
{
    int t = threadIdx.x;
    const long long* p = (const long long*)ei;
    const long long* q = (const long long*)batch;
    long long v1 = p[t];
    long long v2 = q[t];
    int bad1 = (v1 < 0 || v1 >= N_NODESC) ? 1 : 0;
    int bad2 = (v2 < 0 || v2 >= N_GRAPHSC) ? 1 : 0;
    int any1 = __syncthreads_or(bad1);
    int any2 = __syncthreads_or(bad2);
    if (t == 0) { g_i64flag[0] = any1 ? 0 : 1; g_i64flag[1] = any2 ? 0 : 1; }
}
__device__ __forceinline__ int load_edge_idx(const void* ei, int i)
{
    if (g_i64flag[0]) return (int)((const long long*)ei)[i];
    return ((const int*)ei)[i];
}
__device__ __forceinline__ int load_batch_idx(const void* bp, int i)
{
    if (g_i64flag[1]) return (int)((const long long*)bp)[i];
    return ((const int*)bp)[i];
}

// ---------------------------------------------------------------------------
// BF16 split helpers
// ---------------------------------------------------------------------------
__device__ __forceinline__ void bf16_split(float v, __nv_bfloat16& hi, __nv_bfloat16& lo)
{
    hi = __float2bfloat16_rn(v);
    lo = __float2bfloat16_rn(v - __bfloat162float(hi));
}
__device__ __forceinline__ uint32_t bf16_pack(__nv_bfloat16 a, __nv_bfloat16 b)
{
    __nv_bfloat162 p; p.x = a; p.y = b;
    return *(uint32_t*)&p;
}
__device__ __forceinline__ void mma_bf16(float* c, const uint32_t* a, const uint32_t* b)
{
    asm volatile(
        "mma.sync.aligned.m16n8k16.row.col.f32.bf16.bf16.f32 "
        "{%0,%1,%2,%3}, {%4,%5,%6,%7}, {%8,%9}, {%0,%1,%2,%3};"
        : "+f"(c[0]), "+f"(c[1]), "+f"(c[2]), "+f"(c[3])
        : "r"(a[0]), "r"(a[1]), "r"(a[2]), "r"(a[3]), "r"(b[0]), "r"(b[1]));
}
__device__ __forceinline__ uint32_t smem_u32(const void* p)
{
    return (uint32_t)__cvta_generic_to_shared(p);
}
__device__ __forceinline__ void cp_async16(void* s, const void* g)
{
    asm volatile("cp.async.cg.shared.global [%0], [%1], 16;"
                 :: "r"(smem_u32(s)), "l"(g));
}

// split + transpose all weights once: out[col][K] bf16 hi/lo
__global__ void wsplit_kernel(const float* __restrict__ W1,
                              const float* __restrict__ gW,
                              const float* __restrict__ mW)
{
    int i = blockIdx.x * blockDim.x + threadIdx.x;
    if (i >= WS_TOTAL) return;
    float v;
    int oidx;
    if (i < 8192) {
        int k = i >> 7, col = i & 127;
        v = W1[i];
        oidx = WOFF_W1 + col * 64 + k;
    } else if (i < 57344) {
        int j = i - 8192;
        int layer = j >> 14, r = j & 16383;
        int k = r >> 7, col = r & 127;
        v = gW[j];
        oidx = WOFF_G(layer) + col * 128 + k;
    } else {
        int j = i - 57344;
        int k = j >> 7, col = j & 127;
        v = mW[j];
        oidx = WOFF_M + col * 128 + k;
    }
    __nv_bfloat16 hi, lo;
    bf16_split(v, hi, lo);
    g_wbh[oidx] = hi;
    g_wbl[oidx] = lo;
}

// ---------------------------------------------------------------------------
// CSR build: histogram -> 3-kernel scan -> scatter
// ---------------------------------------------------------------------------
__global__ void hist_kernel(const void* __restrict__ ei)
{
    int e = blockIdx.x * blockDim.x + threadIdx.x;
    if (e >= N_EDGESC) return;
    int d = load_edge_idx(ei, e + N_EDGESC);
    atomicAdd(&g_cnt[d], 1);
}

__global__ void scan1_kernel()
{
    __shared__ int s[SCB];
    int t = threadIdx.x;
    int idx = blockIdx.x * SCB + t;
    int v = (idx < N_NODESC) ? g_cnt[idx] : 0;
    s[t] = v;
    __syncthreads();
    for (int o = 1; o < SCB; o <<= 1) {
        int tmp = (t >= o) ? s[t - o] : 0;
        __syncthreads();
        s[t] += tmp;
        __syncthreads();
    }
    if (idx < N_NODESC) g_off[idx] = s[t] - v;
    if (t == SCB - 1) g_bsum[blockIdx.x] = s[t];
}

__global__ void scan2_kernel()
{
    __shared__ int s[256];
    int t = threadIdx.x;
    int v = (t < NSB) ? g_bsum[t] : 0;
    s[t] = v;
    __syncthreads();
    for (int o = 1; o < 256; o <<= 1) {
        int tmp = (t >= o) ? s[t - o] : 0;
        __syncthreads();
        s[t] += tmp;
        __syncthreads();
    }
    if (t < NSB) g_boff[t] = s[t] - v;
}

__global__ void scan3_kernel()
{
    int idx = blockIdx.x * SCB + threadIdx.x;
    if (idx < N_NODESC) {
        int o = g_off[idx] + g_boff[blockIdx.x];
        g_off[idx] = o;
        g_cursor[idx] = o;
    }
    if (idx == 0) g_off[N_NODESC] = N_EDGESC;
}

__global__ void scatter_kernel(const void* __restrict__ ei)
{
    int e = blockIdx.x * blockDim.x + threadIdx.x;
    if (e >= N_EDGESC) return;
    int s = load_edge_idx(ei, e);
    int d = load_edge_idx(ei, e + N_EDGESC);
    int pos = atomicAdd(&g_cursor[d], 1);
    g_csrsrc[pos] = s;
}

__global__ void gbounds_kernel(const void* __restrict__ bp)
{
    int g = blockIdx.x * blockDim.x + threadIdx.x;
    if (g > N_GRAPHSC) return;
    int lo = 0, hi = N_NODESC;
    while (lo < hi) {
        int mid = (lo + hi) >> 1;
        if (load_batch_idx(bp, mid) < g) lo = mid + 1; else hi = mid;
    }
    g_gstart[g] = lo;
}

// ---------------------------------------------------------------------------
// 3xBF16 GEMM, tile 128 rows x 64 cols, BK=32, double-buffered, scalar LDS
// fragment loads (R11-proven). Cf = 32 regs -> 3 CTAs/SM (24 warps) for
// latency hiding. Block 2i+half covers rows [128i,128i+128), cols
// [64*half, 64*half+64). DOTS partial row-dots accumulate via red.global
// (o1/o2 must be zeroed by caller before DOTS launches).
// ---------------------------------------------------------------------------
#define BKB 32
#define ASTR 40
#define ABUF (128 * ASTR)              // 5120 elems / buffer
#define WBUF (64 * ASTR)               // 2560 elems / buffer
#define GEMM_SMEM ((4 * ABUF + 4 * WBUF) * 2)   // 61440 bytes

template<int K, int ACT, int DOTS>
__global__ __launch_bounds__(256, 3)
void gemm_bf16_kernel(const float* __restrict__ A,
                      const __nv_bfloat16* __restrict__ Whi_g,
                      const __nv_bfloat16* __restrict__ Wlo_g,
                      const float* __restrict__ bias, float* __restrict__ Cout,
                      float* __restrict__ o1, float* __restrict__ o2,
                      const float* __restrict__ a1, const float* __restrict__ a2,
                      int M)
{
    extern __shared__ __nv_bfloat16 sdyn[];
    __nv_bfloat16* Ah = sdyn;                    // [2][128][ASTR]
    __nv_bfloat16* Al = Ah + 2 * ABUF;
    __nv_bfloat16* Wh = Al + 2 * ABUF;           // [2][64][ASTR]
    __nv_bfloat16* Wl = Wh + 2 * WBUF;
    __shared__ float asrc_s[64], adst_s[64];
    __shared__ float as_s[128], ad_s[128];

    const int NCH = K / BKB;
    int t = threadIdx.x;
    int wid = t >> 5;
    int lane = t & 31;
    int g = lane >> 2;
    int t4 = lane & 3;
    int mBase = (wid >> 1) * 32;
    int nW = (wid & 1) * 32;
    int row0 = (blockIdx.x >> 1) * 128;
    int colBase = (blockIdx.x & 1) * 64;
    const __nv_bfloat16* WhG = Whi_g + (size_t)colBase * K;
    const __nv_bfloat16* WlG = Wlo_g + (size_t)colBase * K;

    if (DOTS) {
        if (t < 64) { asrc_s[t] = a1[colBase + t]; adst_s[t] = a2[colBase + t]; }
        if (t < 128) { as_s[t] = 0.f; ad_s[t] = 0.f; }
    }

    float Cf[2][4][4];
#pragma unroll
    for (int mt = 0; mt < 2; mt++)
#pragma unroll
        for (int nt = 0; nt < 4; nt++)
#pragma unroll
            for (int i = 0; i < 4; i++) Cf[mt][nt][i] = 0.f;

#define LOADCONV_A(c, p)                                                       \
    {                                                                          \
        _Pragma("unroll")                                                      \
        for (int it = 0; it < 4; it++) {                                       \
            int i = t + it * 256;                                              \
            int r = i >> 3, j = i & 7;                                         \
            int row = row0 + r;                                                \
            float4 v = (row < M)                                               \
                ? *(const float4*)(A + (size_t)row * K + (c) * BKB + j * 4)    \
                : make_float4(0.f, 0.f, 0.f, 0.f);                             \
            __nv_bfloat16 h0, l0, h1, l1, h2, l2, h3, l3;                      \
            bf16_split(v.x, h0, l0); bf16_split(v.y, h1, l1);                  \
            bf16_split(v.z, h2, l2); bf16_split(v.w, h3, l3);                  \
            uint2 ph, pl;                                                      \
            ph.x = bf16_pack(h0, h1); ph.y = bf16_pack(h2, h3);                \
            pl.x = bf16_pack(l0, l1); pl.y = bf16_pack(l2, l3);                \
            *(uint2*)(Ah + (p) * ABUF + r * ASTR + j * 4) = ph;                \
            *(uint2*)(Al + (p) * ABUF + r * ASTR + j * 4) = pl;                \
        }                                                                      \
    }

    // W chunk: 64 cols x 32 bf16 = 256 x 16B per array, 1 per thread
#define CP_W(c, p)                                                             \
    {                                                                          \
        int col = t >> 2, q = t & 3;                                           \
        size_t goff = (size_t)col * K + (c) * BKB + q * 8;                     \
        cp_async16(Wh + (p) * WBUF + col * ASTR + q * 8, WhG + goff);          \
        cp_async16(Wl + (p) * WBUF + col * ASTR + q * 8, WlG + goff);          \
        asm volatile("cp.async.commit_group;");                                \
    }

    // prologue
    CP_W(0, 0);
    LOADCONV_A(0, 0);
    asm volatile("cp.async.wait_group 0;" ::: "memory");
    __syncthreads();

    for (int c = 0; c < NCH; c++) {
        int b = c & 1;
        if (c + 1 < NCH) {
            CP_W(c + 1, 1 - b);
            LOADCONV_A(c + 1, 1 - b);
        }

#pragma unroll
        for (int k16 = 0; k16 < 2; k16++) {
            int kbA = b * ABUF + k16 * 16 + 2 * t4;
            int kbW = b * WBUF + k16 * 16 + 2 * t4;
            uint32_t ah[2][4], al[2][4];
#pragma unroll
            for (int mt = 0; mt < 2; mt++) {
                int wr = mBase + mt * 16 + g;
                ah[mt][0] = *(const uint32_t*)(Ah + kbA + (size_t)wr * ASTR);
                ah[mt][1] = *(const uint32_t*)(Ah + kbA + (size_t)(wr + 8) * ASTR);
                ah[mt][2] = *(const uint32_t*)(Ah + kbA + (size_t)wr * ASTR + 8);
                ah[mt][3] = *(const uint32_t*)(Ah + kbA + (size_t)(wr + 8) * ASTR + 8);
                al[mt][0] = *(const uint32_t*)(Al + kbA + (size_t)wr * ASTR);
                al[mt][1] = *(const uint32_t*)(Al + kbA + (size_t)(wr + 8) * ASTR);
                al[mt][2] = *(const uint32_t*)(Al + kbA + (size_t)wr * ASTR + 8);
                al[mt][3] = *(const uint32_t*)(Al + kbA + (size_t)(wr + 8) * ASTR + 8);
            }
#pragma unroll
            for (int nt = 0; nt < 4; nt++) {
                int cn = nW + nt * 8 + g;
                uint32_t bh[2], bl[2];
                bh[0] = *(const uint32_t*)(Wh + kbW + (size_t)cn * ASTR);
                bh[1] = *(const uint32_t*)(Wh + kbW + (size_t)cn * ASTR + 8);
                bl[0] = *(const uint32_t*)(Wl + kbW + (size_t)cn * ASTR);
                bl[1] = *(const uint32_t*)(Wl + kbW + (size_t)cn * ASTR + 8);
                mma_bf16(Cf[0][nt], ah[0], bh);
                mma_bf16(Cf[1][nt], ah[1], bh);
                mma_bf16(Cf[0][nt], ah[0], bl);
                mma_bf16(Cf[1][nt], ah[1], bl);
                mma_bf16(Cf[0][nt], al[0], bh);
                mma_bf16(Cf[1][nt], al[1], bh);
            }
        }

        if (c + 1 < NCH)
            asm volatile("cp.async.wait_group 0;" ::: "memory");
        __syncthreads();
    }

#pragma unroll
    for (int mt = 0; mt < 2; mt++) {
        int rowA = row0 + mBase + mt * 16 + g;
        int rowB = rowA + 8;
#pragma unroll
        for (int nt = 0; nt < 4; nt++) {
            int colg = colBase + nW + nt * 8 + 2 * t4;
            float c0 = Cf[mt][nt][0], c1 = Cf[mt][nt][1];
            float c2 = Cf[mt][nt][2], c3 = Cf[mt][nt][3];
            if (ACT) {
                float b0 = __ldg(bias + colg), b1 = __ldg(bias + colg + 1);
                c0 += b0; c1 += b1; c2 += b0; c3 += b1;
                c0 = c0 > 0.f ? c0 : 0.01f * c0;
                c1 = c1 > 0.f ? c1 : 0.01f * c1;
                c2 = c2 > 0.f ? c2 : 0.01f * c2;
                c3 = c3 > 0.f ? c3 : 0.01f * c3;
            }
            if (rowA < M) *(float2*)(Cout + (size_t)rowA * HC + colg) = make_float2(c0, c1);
            if (rowB < M) *(float2*)(Cout + (size_t)rowB * HC + colg) = make_float2(c2, c3);
        }
        if (DOTS) {
            float s1a = 0.f, s2a = 0.f, s1b = 0.f, s2b = 0.f;
#pragma unroll
            for (int nt = 0; nt < 4; nt++) {
                int cl = nW + nt * 8 + 2 * t4;
                float w10 = asrc_s[cl], w11 = asrc_s[cl + 1];
                float w20 = adst_s[cl], w21 = adst_s[cl + 1];
                s1a += Cf[mt][nt][0] * w10 + Cf[mt][nt][1] * w11;
                s2a += Cf[mt][nt][0] * w20 + Cf[mt][nt][1] * w21;
                s1b += Cf[mt][nt][2] * w10 + Cf[mt][nt][3] * w11;
                s2b += Cf[mt][nt][2] * w20 + Cf[mt][nt][3] * w21;
            }
            atomicAdd(&as_s[mBase + mt * 16 + g], s1a);
            atomicAdd(&ad_s[mBase + mt * 16 + g], s2a);
            atomicAdd(&as_s[mBase + mt * 16 + g + 8], s1b);
            atomicAdd(&ad_s[mBase + mt * 16 + g + 8], s2b);
        }
    }
    if (DOTS) {
        __syncthreads();
        if (t < 128) {
            int row = row0 + t;
            if (row < M) {
                asm volatile("red.global.add.f32 [%0], %1;"
                             :: "l"(o1 + row), "f"(as_s[t]) : "memory");
                asm volatile("red.global.add.f32 [%0], %1;"
                             :: "l"(o2 + row), "f"(ad_s[t]) : "memory");
            }
        }
    }
#undef LOADCONV_A
#undef CP_W
}

// ---------------------------------------------------------------------------
// Fused GAT aggregation: warp per dst node (CSR), 2-way edge unroll.
// ---------------------------------------------------------------------------
__global__ void gat_agg_kernel(const float* __restrict__ as_n,
                               const float* __restrict__ ad_n,
                               const float* __restrict__ Hs,
                               const float* __restrict__ b,
                               float* __restrict__ Hout)
{
    int gt = blockIdx.x * blockDim.x + threadIdx.x;
    int d = gt >> 5;
    int lane = gt & 31;
    if (d >= N_NODESC) return;
    int start = g_off[d];
    int end   = g_off[d + 1];
    float ad_d = __ldg(ad_n + d);
    float den = 1e-16f;
    float4 acc = make_float4(0.f, 0.f, 0.f, 0.f);
    int j = start;
    for (; j + 1 < end; j += 2) {
        int s0 = __ldg(g_csrsrc + j);
        int s1 = __ldg(g_csrsrc + j + 1);
        float e0 = __ldg(as_n + s0) + ad_d;
        float e1 = __ldg(as_n + s1) + ad_d;
        float4 h0 = __ldg((const float4*)(Hs + (size_t)s0 * HC) + lane);
        float4 h1 = __ldg((const float4*)(Hs + (size_t)s1 * HC) + lane);
        e0 = e0 > 0.f ? e0 : 0.01f * e0;
        e1 = e1 > 0.f ? e1 : 0.01f * e1;
        float x0 = __expf(fminf(e0, 80.f));
        float x1 = __expf(fminf(e1, 80.f));
        den += x0 + x1;
        acc.x += x0 * h0.x + x1 * h1.x;
        acc.y += x0 * h0.y + x1 * h1.y;
        acc.z += x0 * h0.z + x1 * h1.z;
        acc.w += x0 * h0.w + x1 * h1.w;
    }
    if (j < end) {
        int s = __ldg(g_csrsrc + j);
        float e = __ldg(as_n + s) + ad_d;
        e = e > 0.f ? e : 0.01f * e;
        float x = __expf(fminf(e, 80.f));
        den += x;
        float4 hv = __ldg((const float4*)(Hs + (size_t)s * HC) + lane);
        acc.x += x * hv.x; acc.y += x * hv.y;
        acc.z += x * hv.z; acc.w += x * hv.w;
    }
    float r = 1.f / den;
    float4 bb = __ldg((const float4*)b + lane);
    acc.x = acc.x * r + bb.x; acc.y = acc.y * r + bb.y;
    acc.z = acc.z * r + bb.z; acc.w = acc.w * r + bb.w;
    acc.x = acc.x > 0.f ? acc.x : __expf(acc.x) - 1.f;
    acc.y = acc.y > 0.f ? acc.y : __expf(acc.y) - 1.f;
    acc.z = acc.z > 0.f ? acc.z : __expf(acc.z) - 1.f;
    acc.w = acc.w > 0.f ? acc.w : __expf(acc.w) - 1.f;
    ((float4*)(Hout + (size_t)d * HC))[lane] = acc;
}

// ---------------------------------------------------------------------------
// Pooling: warp per graph over contiguous node range, fused ReLU.
// ---------------------------------------------------------------------------
__global__ void pool_kernel(const float* __restrict__ Hn, float* __restrict__ pooled)
{
    int gt = blockIdx.x * blockDim.x + threadIdx.x;
    int gph = gt >> 5;
    int lane = gt & 31;
    if (gph >= N_GRAPHSC) return;
    int n0 = g_gstart[gph], n1 = g_gstart[gph + 1];
    float4 acc = make_float4(0.f, 0.f, 0.f, 0.f);
    for (int n = n0; n < n1; n++) {
        float4 v = __ldg((const float4*)(Hn + (size_t)n * HC) + lane);
        acc.x += v.x; acc.y += v.y; acc.z += v.z; acc.w += v.w;
    }
    acc.x = fmaxf(acc.x, 0.f); acc.y = fmaxf(acc.y, 0.f);
    acc.z = fmaxf(acc.z, 0.f); acc.w = fmaxf(acc.w, 0.f);
    ((float4*)(pooled + (size_t)gph * HC))[lane] = acc;
}

// wv = mW @ m_adst  (warp per row of mW)
__global__ void wadst_kernel(const float* __restrict__ mW,
                             const float* __restrict__ madst,
                             float* __restrict__ wv)
{
    int gt = blockIdx.x * blockDim.x + threadIdx.x;
    int k = gt >> 5;
    int lane = gt & 31;
    if (k >= HC) return;
    float4 m = __ldg((const float4*)(mW + (size_t)k * HC) + lane);
    float4 a = __ldg((const float4*)madst + lane);
    float s = m.x * a.x + m.y * a.y + m.z * a.z + m.w * a.w;
#pragma unroll
    for (int o = 16; o; o >>= 1) s += __shfl_xor_sync(0xFFFFFFFFu, s, o);
    if (lane == 0) wv[k] = s;
}

// adg[g] = pooled[g] . wv
__global__ void adg_kernel(const float* __restrict__ pooled,
                           const float* __restrict__ wv,
                           float* __restrict__ adg)
{
    int gt = blockIdx.x * blockDim.x + threadIdx.x;
    int g = gt >> 5;
    int lane = gt & 31;
    if (g >= N_GRAPHSC) return;
    float4 p = __ldg((const float4*)(pooled + (size_t)g * HC) + lane);
    float4 w = __ldg((const float4*)wv + lane);
    float s = p.x * w.x + p.y * w.y + p.z * w.z + p.w * w.w;
#pragma unroll
    for (int o = 16; o; o >>= 1) s += __shfl_xor_sync(0xFFFFFFFFu, s, o);
    if (lane == 0) adg[g] = s;
}

// ---------------------------------------------------------------------------
// Bipartite readout + final linear, warp per graph.
// ---------------------------------------------------------------------------
__global__ void bip_final_kernel(const float* __restrict__ as_n,
                                 const float* __restrict__ adg,
                                 const float* __restrict__ Hs,
                                 const float* __restrict__ mb,
                                 const float* __restrict__ W2,
                                 const float* __restrict__ b2,
                                 float* __restrict__ out)
{
    int gt = blockIdx.x * blockDim.x + threadIdx.x;
    int gph = gt >> 5;
    int lane = gt & 31;
    if (gph >= N_GRAPHSC) return;
    int n0 = g_gstart[gph], n1 = g_gstart[gph + 1];
    float adg_g = __ldg(adg + gph);
    float den = 1e-16f;
    float4 acc = make_float4(0.f, 0.f, 0.f, 0.f);
    for (int n = n0; n < n1; n++) {
        float e = __ldg(as_n + n) + adg_g;
        e = e > 0.f ? e : 0.01f * e;
        e = fminf(e, 80.f);
        float x = __expf(e);
        den += x;
        float4 hv = __ldg((const float4*)(Hs + (size_t)n * HC) + lane);
        acc.x += x * hv.x; acc.y += x * hv.y;
        acc.z += x * hv.z; acc.w += x * hv.w;
    }
    float r = 1.f / den;
    float4 bb = __ldg((const float4*)mb + lane);
    float4 w2 = __ldg((const float4*)W2 + lane);
    acc.x = acc.x * r + bb.x; acc.y = acc.y * r + bb.y;
    acc.z = acc.z * r + bb.z; acc.w = acc.w * r + bb.w;
    acc.x = acc.x > 0.f ? acc.x : __expf(acc.x) - 1.f;
    acc.y = acc.y > 0.f ? acc.y : __expf(acc.y) - 1.f;
    acc.z = acc.z > 0.f ? acc.z : __expf(acc.z) - 1.f;
    acc.w = acc.w > 0.f ? acc.w : __expf(acc.w) - 1.f;
    float s = acc.x * w2.x + acc.y * w2.y + acc.z * w2.z + acc.w * w2.w;
#pragma unroll
    for (int o = 16; o; o >>= 1) s += __shfl_xor_sync(0xFFFFFFFFu, s, o);
    if (lane == 0) out[gph] = s + b2[0];
}

// ---------------------------------------------------------------------------
// Host launcher
// ---------------------------------------------------------------------------
extern "C" void kernel_launch(void* const* d_in, const int* in_sizes, int n_in,
                              void* d_out, int out_size)
{
    (void)in_sizes; (void)n_in; (void)out_size;
    const float* x     = (const float*)d_in[0];
    const void*  ei    = d_in[1];
    const void*  batch = d_in[2];
    const float* W1    = (const float*)d_in[3];
    const float* b1    = (const float*)d_in[4];
    const float* gW    = (const float*)d_in[5];
    const float* gasrc = (const float*)d_in[6];
    const float* gadst = (const float*)d_in[7];
    const float* gb    = (const float*)d_in[8];
    const float* mW    = (const float*)d_in[9];
    const float* masrc = (const float*)d_in[10];
    const float* madst = (const float*)d_in[11];
    const float* mb    = (const float*)d_in[12];
    const float* W2    = (const float*)d_in[13];
    const float* b2    = (const float*)d_in[14];
    float* out = (float*)d_out;

    float *h, *hs, *as_, *ad_, *pooled, *adg, *wv;
    __nv_bfloat16 *wbh, *wbl;
    int* cnt;
    cudaGetSymbolAddress((void**)&h,      g_h);
    cudaGetSymbolAddress((void**)&hs,     g_hs);
    cudaGetSymbolAddress((void**)&as_,    g_as);
    cudaGetSymbolAddress((void**)&ad_,    g_ad);
    cudaGetSymbolAddress((void**)&pooled, g_pooled);
    cudaGetSymbolAddress((void**)&adg,    g_adg);
    cudaGetSymbolAddress((void**)&wv,     g_wv);
    cudaGetSymbolAddress((void**)&wbh,    g_wbh);
    cudaGetSymbolAddress((void**)&wbl,    g_wbl);
    cudaGetSymbolAddress((void**)&cnt,    g_cnt);

    // raise dynamic smem limit (idempotent device config, not an allocation)
    cudaFuncSetAttribute(gemm_bf16_kernel<F_INC, 1, 0>,
                         cudaFuncAttributeMaxDynamicSharedMemorySize, GEMM_SMEM);
    cudaFuncSetAttribute(gemm_bf16_kernel<HC, 0, 1>,
                         cudaFuncAttributeMaxDynamicSharedMemorySize, GEMM_SMEM);

    const int T = 256;
    const int edgeBlocks      = (N_EDGESC + T - 1) / T;
    const int nodeWarpBlocks  = (N_NODESC * 32 + T - 1) / T;
    const int graphWarpBlocks = (N_GRAPHSC * 32 + T - 1) / T;
    const int gemmBlocksN = 2 * ((N_NODESC + 127) / 128);   // 2 col-halves

    detect_kernel<<<1, 256>>>(ei, batch);
    wsplit_kernel<<<(WS_TOTAL + T - 1) / T, T>>>(W1, gW, mW);
    gemm_bf16_kernel<F_INC, 1, 0><<<gemmBlocksN, T, GEMM_SMEM>>>(
        x, wbh + WOFF_W1, wbl + WOFF_W1, b1, h,
        nullptr, nullptr, nullptr, nullptr, N_NODESC);
    cudaMemsetAsync(as_, 0, N_NODESC * sizeof(float));
    cudaMemsetAsync(ad_, 0, N_NODESC * sizeof(float));
    gemm_bf16_kernel<HC, 0, 1><<<gemmBlocksN, T, GEMM_SMEM>>>(
        h, wbh + WOFF_G(0), wbl + WOFF_G(0), nullptr, hs,
        as_, ad_, gasrc, gadst, N_NODESC);

    // CSR build + graph boundaries
    cudaMemsetAsync(cnt, 0, N_NODESC * sizeof(int));
    hist_kernel<<<edgeBlocks, T>>>(ei);
    scan1_kernel<<<NSB, SCB>>>();
    scan2_kernel<<<1, 256>>>();
    scan3_kernel<<<NSB, SCB>>>();
    scatter_kernel<<<edgeBlocks, T>>>(ei);
    gbounds_kernel<<<(N_GRAPHSC + 1 + T - 1) / T, T>>>(batch);

    // layer 0 aggregation, then layers 1..2
    gat_agg_kernel<<<nodeWarpBlocks, T>>>(as_, ad_, hs, gb, h);
    for (int i = 1; i < 3; i++) {
        cudaMemsetAsync(as_, 0, N_NODESC * sizeof(float));
        cudaMemsetAsync(ad_, 0, N_NODESC * sizeof(float));
        gemm_bf16_kernel<HC, 0, 1><<<gemmBlocksN, T, GEMM_SMEM>>>(
            h, wbh + WOFF_G(i), wbl + WOFF_G(i), nullptr, hs,
            as_, ad_, gasrc + i * HC, gadst + i * HC, N_NODESC);
        gat_agg_kernel<<<nodeWarpBlocks, T>>>(as_, ad_, hs, gb + i * HC, h);
    }

    // pooled = relu(segment_sum(h, batch))
    pool_kernel<<<graphWarpBlocks, T>>>(h, pooled);

    // node-side projection; graph side reduced to adg = pooled @ (mW @ m_adst)
    cudaMemsetAsync(as_, 0, N_NODESC * sizeof(float));
    cudaMemsetAsync(ad_, 0, N_NODESC * sizeof(float));
    gemm_bf16_kernel<HC, 0, 1><<<gemmBlocksN, T, GEMM_SMEM>>>(
        h, wbh + WOFF_M, wbl + WOFF_M, nullptr, hs, as_, ad_, masrc, madst, N_NODESC);
    wadst_kernel<<<(HC * 32 + T - 1) / T, T>>>(mW, madst, wv);
    adg_kernel<<<graphWarpBlocks, T>>>(pooled, wv, adg);

    // fused bipartite attention + ELU + final linear
    bip_final_kernel<<<graphWarpBlocks, T>>>(as_, adg, hs, mb, W2, b2, out);
}

// round 15
// speedup vs baseline: 1.1834x; 1.1834x over previous
#include <cuda_runtime.h>
#include <cuda_bf16.h>
#include <cstdint>
#include <math.h>

#define N_NODESC 100000
#define N_EDGESC 400000
#define N_GRAPHSC 5000
#define F_INC 64
#define HC 128

// ---------------------------------------------------------------------------
// Scratch
// ---------------------------------------------------------------------------
__device__ __align__(16) float g_h   [(size_t)N_NODESC * HC];
__device__ __align__(16) float g_hagg[(size_t)N_NODESC * HC];
__device__ __align__(16) float g_as  [N_NODESC];
__device__ __align__(16) float g_ad  [N_NODESC];
__device__ __align__(16) float g_pooled[(size_t)N_GRAPHSC * HC];
__device__ __align__(16) float g_adg [N_GRAPHSC];
__device__ __align__(16) float g_uv  [1024];   // [2][4][128]: u/v per layer + mW
// pre-split, pre-TRANSPOSED bf16 weights, layout [col][K]
#define WS_TOTAL (576 * 128)
#define WOFF_W1 0
#define WOFF_G(i) (8192 + (i) * 16384)
#define WOFF_M 57344
__device__ __align__(16) __nv_bfloat16 g_wbh[WS_TOTAL];
__device__ __align__(16) __nv_bfloat16 g_wbl[WS_TOTAL];
// CSR by destination
#define SCB 512
#define NSB ((N_NODESC + SCB - 1) / SCB)
__device__ int g_cnt   [N_NODESC];
__device__ int g_off   [N_NODESC + 1];
__device__ int g_cursor[N_NODESC];
__device__ int g_csrsrc[N_EDGESC];
__device__ int g_bsum  [NSB];
__device__ int g_boff  [NSB];
__device__ int g_gstart[N_GRAPHSC + 1];
__device__ int g_i64flag[2];

// ---------------------------------------------------------------------------
// dtype detection (int64 vs int32 indices)
// ---------------------------------------------------------------------------
__global__ void detect_kernel(const void* ei, const void* batch)
{
    int t = threadIdx.x;
    const long long* p = (const long long*)ei;
    const long long* q = (const long long*)batch;
    long long v1 = p[t];
    long long v2 = q[t];
    int bad1 = (v1 < 0 || v1 >= N_NODESC) ? 1 : 0;
    int bad2 = (v2 < 0 || v2 >= N_GRAPHSC) ? 1 : 0;
    int any1 = __syncthreads_or(bad1);
    int any2 = __syncthreads_or(bad2);
    if (t == 0) { g_i64flag[0] = any1 ? 0 : 1; g_i64flag[1] = any2 ? 0 : 1; }
}
__device__ __forceinline__ int load_edge_idx(const void* ei, int i)
{
    if (g_i64flag[0]) return (int)((const long long*)ei)[i];
    return ((const int*)ei)[i];
}
__device__ __forceinline__ int load_batch_idx(const void* bp, int i)
{
    if (g_i64flag[1]) return (int)((const long long*)bp)[i];
    return ((const int*)bp)[i];
}

// ---------------------------------------------------------------------------
// BF16 split helpers
// ---------------------------------------------------------------------------
__device__ __forceinline__ void bf16_split(float v, __nv_bfloat16& hi, __nv_bfloat16& lo)
{
    hi = __float2bfloat16_rn(v);
    lo = __float2bfloat16_rn(v - __bfloat162float(hi));
}
__device__ __forceinline__ uint32_t bf16_pack(__nv_bfloat16 a, __nv_bfloat16 b)
{
    __nv_bfloat162 p; p.x = a; p.y = b;
    return *(uint32_t*)&p;
}
__device__ __forceinline__ void mma_bf16(float* c, const uint32_t* a, const uint32_t* b)
{
    asm volatile(
        "mma.sync.aligned.m16n8k16.row.col.f32.bf16.bf16.f32 "
        "{%0,%1,%2,%3}, {%4,%5,%6,%7}, {%8,%9}, {%0,%1,%2,%3};"
        : "+f"(c[0]), "+f"(c[1]), "+f"(c[2]), "+f"(c[3])
        : "r"(a[0]), "r"(a[1]), "r"(a[2]), "r"(a[3]), "r"(b[0]), "r"(b[1]));
}
__device__ __forceinline__ uint32_t smem_u32(const void* p)
{
    return (uint32_t)__cvta_generic_to_shared(p);
}
__device__ __forceinline__ void cp_async16(void* s, const void* g)
{
    asm volatile("cp.async.cg.shared.global [%0], [%1], 16;"
                 :: "r"(smem_u32(s)), "l"(g));
}

// split + transpose all weights once: out[col][K] bf16 hi/lo
__global__ void wsplit_kernel(const float* __restrict__ W1,
                              const float* __restrict__ gW,
                              const float* __restrict__ mW)
{
    int i = blockIdx.x * blockDim.x + threadIdx.x;
    if (i >= WS_TOTAL) return;
    float v;
    int oidx;
    if (i < 8192) {
        int k = i >> 7, col = i & 127;
        v = W1[i];
        oidx = WOFF_W1 + col * 64 + k;
    } else if (i < 57344) {
        int j = i - 8192;
        int layer = j >> 14, r = j & 16383;
        int k = r >> 7, col = r & 127;
        v = gW[j];
        oidx = WOFF_G(layer) + col * 128 + k;
    } else {
        int j = i - 57344;
        int k = j >> 7, col = j & 127;
        v = mW[j];
        oidx = WOFF_M + col * 128 + k;
    }
    __nv_bfloat16 hi, lo;
    bf16_split(v, hi, lo);
    g_wbh[oidx] = hi;
    g_wbl[oidx] = lo;
}

// uv[which][p][k] = sum_c Wp[k][c] * vec_p[c]; which 0: a_src, 1: a_dst.
// p = 0..2 -> gW layers, p = 3 -> mW with masrc/madst.
__global__ void uv_kernel(const float* __restrict__ gW,
                          const float* __restrict__ gasrc,
                          const float* __restrict__ gadst,
                          const float* __restrict__ mW,
                          const float* __restrict__ masrc,
                          const float* __restrict__ madst,
                          float* __restrict__ uv)
{
    int gt = blockIdx.x * blockDim.x + threadIdx.x;
    int id = gt >> 5;
    int lane = gt & 31;
    if (id >= 1024) return;
    int which = id >> 9;
    int p = (id >> 7) & 3;
    int k = id & 127;
    const float* W = (p < 3) ? gW + (size_t)p * 16384 : mW;
    const float* a = (p < 3) ? ((which == 0 ? gasrc : gadst) + p * 128)
                             : (which == 0 ? masrc : madst);
    float4 m = __ldg((const float4*)(W + (size_t)k * 128) + lane);
    float4 av = __ldg((const float4*)a + lane);
    float s = m.x * av.x + m.y * av.y + m.z * av.z + m.w * av.w;
#pragma unroll
    for (int o = 16; o; o >>= 1) s += __shfl_xor_sync(0xFFFFFFFFu, s, o);
    if (lane == 0) uv[which * 512 + p * 128 + k] = s;
}

// ---------------------------------------------------------------------------
// CSR build: histogram -> 3-kernel scan -> scatter
// ---------------------------------------------------------------------------
__global__ void hist_kernel(const void* __restrict__ ei)
{
    int e = blockIdx.x * blockDim.x + threadIdx.x;
    if (e >= N_EDGESC) return;
    atomicAdd(&g_cnt[load_edge_idx(ei, e + N_EDGESC)], 1);
}
__global__ void scan1_kernel()
{
    __shared__ int s[SCB];
    int t = threadIdx.x;
    int idx = blockIdx.x * SCB + t;
    int v = (idx < N_NODESC) ? g_cnt[idx] : 0;
    s[t] = v;
    __syncthreads();
    for (int o = 1; o < SCB; o <<= 1) {
        int tmp = (t >= o) ? s[t - o] : 0;
        __syncthreads();
        s[t] += tmp;
        __syncthreads();
    }
    if (idx < N_NODESC) g_off[idx] = s[t] - v;
    if (t == SCB - 1) g_bsum[blockIdx.x] = s[t];
}
__global__ void scan2_kernel()
{
    __shared__ int s[256];
    int t = threadIdx.x;
    int v = (t < NSB) ? g_bsum[t] : 0;
    s[t] = v;
    __syncthreads();
    for (int o = 1; o < 256; o <<= 1) {
        int tmp = (t >= o) ? s[t - o] : 0;
        __syncthreads();
        s[t] += tmp;
        __syncthreads();
    }
    if (t < NSB) g_boff[t] = s[t] - v;
}
__global__ void scan3_kernel()
{
    int idx = blockIdx.x * SCB + threadIdx.x;
    if (idx < N_NODESC) {
        int o = g_off[idx] + g_boff[blockIdx.x];
        g_off[idx] = o;
        g_cursor[idx] = o;
    }
    if (idx == 0) g_off[N_NODESC] = N_EDGESC;
}
__global__ void scatter_kernel(const void* __restrict__ ei)
{
    int e = blockIdx.x * blockDim.x + threadIdx.x;
    if (e >= N_EDGESC) return;
    int s = load_edge_idx(ei, e);
    int d = load_edge_idx(ei, e + N_EDGESC);
    g_csrsrc[atomicAdd(&g_cursor[d], 1)] = s;
}
__global__ void gbounds_kernel(const void* __restrict__ bp)
{
    int g = blockIdx.x * blockDim.x + threadIdx.x;
    if (g > N_GRAPHSC) return;
    int lo = 0, hi = N_NODESC;
    while (lo < hi) {
        int mid = (lo + hi) >> 1;
        if (load_batch_idx(bp, mid) < g) lo = mid + 1; else hi = mid;
    }
    g_gstart[g] = lo;
}

// ---------------------------------------------------------------------------
// 3xBF16 GEMM (R11-proven core): C[M,128] = A[M,K] @ W[K,128], BK=32,
// fully double-buffered dynamic smem, scalar LDS fragments.
// ACT: 0 none, 1 bias+leaky(0.01), 2 bias+ELU.
// DOTS: o1[row] = C_act[row,:].a1, o2[row] = C_act[row,:].a2 (post-activation,
// matching as = h.u ordering). Direct stores, no atomics.
// ---------------------------------------------------------------------------
#define BKB 32
#define ASTR 40
#define BUFE (128 * ASTR)
#define GEMM_SMEM (8 * BUFE * 2)       // 81920 bytes

template<int K, int ACT, int DOTS>
__global__ __launch_bounds__(256, 2)
void gemm_bf16_kernel(const float* __restrict__ A,
                      const __nv_bfloat16* __restrict__ Whi_g,
                      const __nv_bfloat16* __restrict__ Wlo_g,
                      const float* __restrict__ bias, float* __restrict__ Cout,
                      float* __restrict__ o1, float* __restrict__ o2,
                      const float* __restrict__ a1, const float* __restrict__ a2,
                      int M)
{
    extern __shared__ __nv_bfloat16 sdyn[];
    __nv_bfloat16* Ah = sdyn;
    __nv_bfloat16* Al = Ah + 2 * BUFE;
    __nv_bfloat16* Wh = Al + 2 * BUFE;
    __nv_bfloat16* Wl = Wh + 2 * BUFE;
    __shared__ float asrc_s[HC], adst_s[HC];
    __shared__ float as_s[128], ad_s[128];

    const int NCH = K / BKB;
    int t = threadIdx.x;
    int wid = t >> 5;
    int lane = t & 31;
    int g = lane >> 2;
    int t4 = lane & 3;
    int mBase = (wid >> 1) * 32;
    int nWarp = (wid & 1) * 64;
    int row0 = blockIdx.x * 128;

    if (DOTS) {
        if (t < 128) { asrc_s[t] = a1[t]; adst_s[t] = a2[t]; as_s[t] = 0.f; ad_s[t] = 0.f; }
    }

    float Cf[2][8][4];
#pragma unroll
    for (int mt = 0; mt < 2; mt++)
#pragma unroll
        for (int nt = 0; nt < 8; nt++)
#pragma unroll
            for (int i = 0; i < 4; i++) Cf[mt][nt][i] = 0.f;

    float4 aReg[4];

#define LOAD_A(c)                                                              \
    {                                                                          \
        _Pragma("unroll")                                                      \
        for (int it = 0; it < 4; it++) {                                       \
            int i = t + it * 256;                                              \
            int r = i >> 3, j = i & 7;                                         \
            int row = row0 + r;                                                \
            aReg[it] = (row < M)                                               \
                ? *(const float4*)(A + (size_t)row * K + (c) * BKB + j * 4)    \
                : make_float4(0.f, 0.f, 0.f, 0.f);                             \
        }                                                                      \
    }

#define CONV_A(p)                                                              \
    {                                                                          \
        _Pragma("unroll")                                                      \
        for (int it = 0; it < 4; it++) {                                       \
            int i = t + it * 256;                                              \
            int r = i >> 3, j = i & 7;                                         \
            float4 v = aReg[it];                                               \
            __nv_bfloat16 h0, l0, h1, l1, h2, l2, h3, l3;                      \
            bf16_split(v.x, h0, l0); bf16_split(v.y, h1, l1);                  \
            bf16_split(v.z, h2, l2); bf16_split(v.w, h3, l3);                  \
            uint2 ph, pl;                                                      \
            ph.x = bf16_pack(h0, h1); ph.y = bf16_pack(h2, h3);                \
            pl.x = bf16_pack(l0, l1); pl.y = bf16_pack(l2, l3);                \
            *(uint2*)(Ah + (p) * BUFE + r * ASTR + j * 4) = ph;                \
            *(uint2*)(Al + (p) * BUFE + r * ASTR + j * 4) = pl;                \
        }                                                                      \
    }

#define CP_W(c, p)                                                             \
    {                                                                          \
        _Pragma("unroll")                                                      \
        for (int it = 0; it < 2; it++) {                                       \
            int i = t + it * 256;                                              \
            int col = i >> 2, q = i & 3;                                       \
            size_t goff = (size_t)col * K + (c) * BKB + q * 8;                 \
            cp_async16(Wh + (p) * BUFE + col * ASTR + q * 8, Whi_g + goff);    \
            cp_async16(Wl + (p) * BUFE + col * ASTR + q * 8, Wlo_g + goff);    \
        }                                                                      \
        asm volatile("cp.async.commit_group;");                                \
    }

    LOAD_A(0);
    CP_W(0, 0);
    CONV_A(0);
    if (NCH > 1) LOAD_A(1);
    asm volatile("cp.async.wait_group 0;" ::: "memory");
    __syncthreads();

    for (int c = 0; c < NCH; c++) {
        int b = c & 1;
        if (c + 1 < NCH) {
            CP_W(c + 1, 1 - b);
            CONV_A(1 - b);
            if (c + 2 < NCH) LOAD_A(c + 2);
        }

#pragma unroll
        for (int k16 = 0; k16 < 2; k16++) {
            int kb = b * BUFE + k16 * 16 + 2 * t4;
            uint32_t ah[2][4], al[2][4];
#pragma unroll
            for (int mt = 0; mt < 2; mt++) {
                int wr = mBase + mt * 16 + g;
                ah[mt][0] = *(const uint32_t*)(Ah + kb + (size_t)wr * ASTR);
                ah[mt][1] = *(const uint32_t*)(Ah + kb + (size_t)(wr + 8) * ASTR);
                ah[mt][2] = *(const uint32_t*)(Ah + kb + (size_t)wr * ASTR + 8);
                ah[mt][3] = *(const uint32_t*)(Ah + kb + (size_t)(wr + 8) * ASTR + 8);
                al[mt][0] = *(const uint32_t*)(Al + kb + (size_t)wr * ASTR);
                al[mt][1] = *(const uint32_t*)(Al + kb + (size_t)(wr + 8) * ASTR);
                al[mt][2] = *(const uint32_t*)(Al + kb + (size_t)wr * ASTR + 8);
                al[mt][3] = *(const uint32_t*)(Al + kb + (size_t)(wr + 8) * ASTR + 8);
            }
#pragma unroll
            for (int nt = 0; nt < 8; nt++) {
                int cn = nWarp + nt * 8 + g;
                uint32_t bh[2], bl[2];
                bh[0] = *(const uint32_t*)(Wh + kb + (size_t)cn * ASTR);
                bh[1] = *(const uint32_t*)(Wh + kb + (size_t)cn * ASTR + 8);
                bl[0] = *(const uint32_t*)(Wl + kb + (size_t)cn * ASTR);
                bl[1] = *(const uint32_t*)(Wl + kb + (size_t)cn * ASTR + 8);
                mma_bf16(Cf[0][nt], ah[0], bh);
                mma_bf16(Cf[1][nt], ah[1], bh);
                mma_bf16(Cf[0][nt], ah[0], bl);
                mma_bf16(Cf[1][nt], ah[1], bl);
                mma_bf16(Cf[0][nt], al[0], bh);
                mma_bf16(Cf[1][nt], al[1], bh);
            }
        }

        if (c + 1 < NCH)
            asm volatile("cp.async.wait_group 0;" ::: "memory");
        __syncthreads();
    }

#pragma unroll
    for (int mt = 0; mt < 2; mt++) {
        int rowA = row0 + mBase + mt * 16 + g;
        int rowB = rowA + 8;
        float s1a = 0.f, s2a = 0.f, s1b = 0.f, s2b = 0.f;
#pragma unroll
        for (int nt = 0; nt < 8; nt++) {
            int col = nWarp + nt * 8 + 2 * t4;
            float c0 = Cf[mt][nt][0], c1 = Cf[mt][nt][1];
            float c2 = Cf[mt][nt][2], c3 = Cf[mt][nt][3];
            if (ACT) {
                float b0 = __ldg(bias + col), b1 = __ldg(bias + col + 1);
                c0 += b0; c1 += b1; c2 += b0; c3 += b1;
                if (ACT == 1) {
                    c0 = c0 > 0.f ? c0 : 0.01f * c0;
                    c1 = c1 > 0.f ? c1 : 0.01f * c1;
                    c2 = c2 > 0.f ? c2 : 0.01f * c2;
                    c3 = c3 > 0.f ? c3 : 0.01f * c3;
                } else {
                    c0 = c0 > 0.f ? c0 : __expf(c0) - 1.f;
                    c1 = c1 > 0.f ? c1 : __expf(c1) - 1.f;
                    c2 = c2 > 0.f ? c2 : __expf(c2) - 1.f;
                    c3 = c3 > 0.f ? c3 : __expf(c3) - 1.f;
                }
            }
            if (rowA < M) *(float2*)(Cout + (size_t)rowA * HC + col) = make_float2(c0, c1);
            if (rowB < M) *(float2*)(Cout + (size_t)rowB * HC + col) = make_float2(c2, c3);
            if (DOTS) {
                float w10 = asrc_s[col], w11 = asrc_s[col + 1];
                float w20 = adst_s[col], w21 = adst_s[col + 1];
                s1a += c0 * w10 + c1 * w11;
                s2a += c0 * w20 + c1 * w21;
                s1b += c2 * w10 + c3 * w11;
                s2b += c2 * w20 + c3 * w21;
            }
        }
        if (DOTS) {
            atomicAdd(&as_s[mBase + mt * 16 + g], s1a);
            atomicAdd(&ad_s[mBase + mt * 16 + g], s2a);
            atomicAdd(&as_s[mBase + mt * 16 + g + 8], s1b);
            atomicAdd(&ad_s[mBase + mt * 16 + g + 8], s2b);
        }
    }
    if (DOTS) {
        __syncthreads();
        if (t < 128) {
            int row = row0 + t;
            if (row < M) { o1[row] = as_s[t]; o2[row] = ad_s[t]; }
        }
    }
#undef LOAD_A
#undef CONV_A
#undef CP_W
}

// ---------------------------------------------------------------------------
// GAT aggregation: warp per dst node (CSR), 2-way unroll; stores the
// NORMALIZED weighted sum (projection + bias + ELU happen in the next GEMM).
// ---------------------------------------------------------------------------
__global__ void gat_agg_kernel(const float* __restrict__ as_n,
                               const float* __restrict__ ad_n,
                               const float* __restrict__ Hn,
                               float* __restrict__ Hagg)
{
    int gt = blockIdx.x * blockDim.x + threadIdx.x;
    int d = gt >> 5;
    int lane = gt & 31;
    if (d >= N_NODESC) return;
    int start = g_off[d];
    int end   = g_off[d + 1];
    float ad_d = __ldg(ad_n + d);
    float den = 1e-16f;
    float4 acc = make_float4(0.f, 0.f, 0.f, 0.f);
    int j = start;
    for (; j + 1 < end; j += 2) {
        int s0 = __ldg(g_csrsrc + j);
        int s1 = __ldg(g_csrsrc + j + 1);
        float e0 = __ldg(as_n + s0) + ad_d;
        float e1 = __ldg(as_n + s1) + ad_d;
        float4 h0 = __ldg((const float4*)(Hn + (size_t)s0 * HC) + lane);
        float4 h1 = __ldg((const float4*)(Hn + (size_t)s1 * HC) + lane);
        e0 = e0 > 0.f ? e0 : 0.01f * e0;
        e1 = e1 > 0.f ? e1 : 0.01f * e1;
        float x0 = __expf(fminf(e0, 80.f));
        float x1 = __expf(fminf(e1, 80.f));
        den += x0 + x1;
        acc.x += x0 * h0.x + x1 * h1.x;
        acc.y += x0 * h0.y + x1 * h1.y;
        acc.z += x0 * h0.z + x1 * h1.z;
        acc.w += x0 * h0.w + x1 * h1.w;
    }
    if (j < end) {
        int s = __ldg(g_csrsrc + j);
        float e = __ldg(as_n + s) + ad_d;
        e = e > 0.f ? e : 0.01f * e;
        float x = __expf(fminf(e, 80.f));
        den += x;
        float4 hv = __ldg((const float4*)(Hn + (size_t)s * HC) + lane);
        acc.x += x * hv.x; acc.y += x * hv.y;
        acc.z += x * hv.z; acc.w += x * hv.w;
    }
    float r = 1.f / den;
    acc.x *= r; acc.y *= r; acc.z *= r; acc.w *= r;
    ((float4*)(Hagg + (size_t)d * HC))[lane] = acc;
}

// ---------------------------------------------------------------------------
// Pooling: warp per graph over contiguous node range, fused ReLU.
// ---------------------------------------------------------------------------
__global__ void pool_kernel(const float* __restrict__ Hn, float* __restrict__ pooled)
{
    int gt = blockIdx.x * blockDim.x + threadIdx.x;
    int gph = gt >> 5;
    int lane = gt & 31;
    if (gph >= N_GRAPHSC) return;
    int n0 = g_gstart[gph], n1 = g_gstart[gph + 1];
    float4 acc = make_float4(0.f, 0.f, 0.f, 0.f);
    for (int n = n0; n < n1; n++) {
        float4 v = __ldg((const float4*)(Hn + (size_t)n * HC) + lane);
        acc.x += v.x; acc.y += v.y; acc.z += v.z; acc.w += v.w;
    }
    acc.x = fmaxf(acc.x, 0.f); acc.y = fmaxf(acc.y, 0.f);
    acc.z = fmaxf(acc.z, 0.f); acc.w = fmaxf(acc.w, 0.f);
    ((float4*)(pooled + (size_t)gph * HC))[lane] = acc;
}

// adg[g] = pooled[g] . v3   (== (pooled@mW).m_adst)
__global__ void adg_kernel(const float* __restrict__ pooled,
                           const float* __restrict__ v3,
                           float* __restrict__ adg)
{
    int gt = blockIdx.x * blockDim.x + threadIdx.x;
    int g = gt >> 5;
    int lane = gt & 31;
    if (g >= N_GRAPHSC) return;
    float4 p = __ldg((const float4*)(pooled + (size_t)g * HC) + lane);
    float4 w = __ldg((const float4*)v3 + lane);
    float s = p.x * w.x + p.y * w.y + p.z * w.z + p.w * w.w;
#pragma unroll
    for (int o = 16; o; o >>= 1) s += __shfl_xor_sync(0xFFFFFFFFu, s, o);
    if (lane == 0) adg[g] = s;
}

// ---------------------------------------------------------------------------
// Final: warp per graph. gacc = (sum_n x_n h_n)/den over graph's nodes
// (x from as + adg), then out = elu(gacc @ mW + mb) . W2 + b2.
// Uses segment_sum(alpha*(h@mW)) = (segment_sum(alpha*h)) @ mW.
// ---------------------------------------------------------------------------
__global__ void final_kernel(const float* __restrict__ as_n,
                             const float* __restrict__ adg,
                             const float* __restrict__ Hn,
                             const float* __restrict__ mW,
                             const float* __restrict__ mb,
                             const float* __restrict__ W2,
                             const float* __restrict__ b2,
                             float* __restrict__ out)
{
    int gt = blockIdx.x * blockDim.x + threadIdx.x;
    int gph = gt >> 5;
    int lane = gt & 31;
    if (gph >= N_GRAPHSC) return;
    int n0 = g_gstart[gph], n1 = g_gstart[gph + 1];
    float adg_g = __ldg(adg + gph);
    float den = 1e-16f;
    float4 acc = make_float4(0.f, 0.f, 0.f, 0.f);
    for (int n = n0; n < n1; n++) {
        float e = __ldg(as_n + n) + adg_g;
        e = e > 0.f ? e : 0.01f * e;
        e = fminf(e, 80.f);
        float x = __expf(e);
        den += x;
        float4 hv = __ldg((const float4*)(Hn + (size_t)n * HC) + lane);
        acc.x += x * hv.x; acc.y += x * hv.y;
        acc.z += x * hv.z; acc.w += x * hv.w;
    }
    float r = 1.f / den;
    acc.x *= r; acc.y *= r; acc.z *= r; acc.w *= r;   // gacc components k=4*lane..+3

    // matvec: o[c] = sum_k gacc[k]*mW[k][c], lane owns c = 4*lane..4*lane+3
    float4 o = make_float4(0.f, 0.f, 0.f, 0.f);
#pragma unroll
    for (int sl = 0; sl < 32; sl++) {
        float gx = __shfl_sync(0xFFFFFFFFu, acc.x, sl);
        float gy = __shfl_sync(0xFFFFFFFFu, acc.y, sl);
        float gz = __shfl_sync(0xFFFFFFFFu, acc.z, sl);
        float gw = __shfl_sync(0xFFFFFFFFu, acc.w, sl);
        int k0 = sl * 4;
        float4 w0 = __ldg((const float4*)(mW + (size_t)(k0 + 0) * HC) + lane);
        float4 w1 = __ldg((const float4*)(mW + (size_t)(k0 + 1) * HC) + lane);
        float4 w2 = __ldg((const float4*)(mW + (size_t)(k0 + 2) * HC) + lane);
        float4 w3 = __ldg((const float4*)(mW + (size_t)(k0 + 3) * HC) + lane);
        o.x += gx * w0.x + gy * w1.x + gz * w2.x + gw * w3.x;
        o.y += gx * w0.y + gy * w1.y + gz * w2.y + gw * w3.y;
        o.z += gx * w0.z + gy * w1.z + gz * w2.z + gw * w3.z;
        o.w += gx * w0.w + gy * w1.w + gz * w2.w + gw * w3.w;
    }
    float4 bb = __ldg((const float4*)mb + lane);
    float4 w2v = __ldg((const float4*)W2 + lane);
    o.x += bb.x; o.y += bb.y; o.z += bb.z; o.w += bb.w;
    o.x = o.x > 0.f ? o.x : __expf(o.x) - 1.f;
    o.y = o.y > 0.f ? o.y : __expf(o.y) - 1.f;
    o.z = o.z > 0.f ? o.z : __expf(o.z) - 1.f;
    o.w = o.w > 0.f ? o.w : __expf(o.w) - 1.f;
    float s = o.x * w2v.x + o.y * w2v.y + o.z * w2v.z + o.w * w2v.w;
#pragma unroll
    for (int off = 16; off; off >>= 1) s += __shfl_xor_sync(0xFFFFFFFFu, s, off);
    if (lane == 0) out[gph] = s + b2[0];
}

// ---------------------------------------------------------------------------
// Host launcher
// ---------------------------------------------------------------------------
extern "C" void kernel_launch(void* const* d_in, const int* in_sizes, int n_in,
                              void* d_out, int out_size)
{
    (void)in_sizes; (void)n_in; (void)out_size;
    const float* x     = (const float*)d_in[0];
    const void*  ei    = d_in[1];
    const void*  batch = d_in[2];
    const float* W1    = (const float*)d_in[3];
    const float* b1    = (const float*)d_in[4];
    const float* gW    = (const float*)d_in[5];
    const float* gasrc = (const float*)d_in[6];
    const float* gadst = (const float*)d_in[7];
    const float* gb    = (const float*)d_in[8];
    const float* mW    = (const float*)d_in[9];
    const float* masrc = (const float*)d_in[10];
    const float* madst = (const float*)d_in[11];
    const float* mb    = (const float*)d_in[12];
    const float* W2    = (const float*)d_in[13];
    const float* b2    = (const float*)d_in[14];
    float* out = (float*)d_out;

    float *h, *hagg, *as_, *ad_, *pooled, *adg, *uv;
    __nv_bfloat16 *wbh, *wbl;
    int* cnt;
    cudaGetSymbolAddress((void**)&h,      g_h);
    cudaGetSymbolAddress((void**)&hagg,   g_hagg);
    cudaGetSymbolAddress((void**)&as_,    g_as);
    cudaGetSymbolAddress((void**)&ad_,    g_ad);
    cudaGetSymbolAddress((void**)&pooled, g_pooled);
    cudaGetSymbolAddress((void**)&adg,    g_adg);
    cudaGetSymbolAddress((void**)&uv,     g_uv);
    cudaGetSymbolAddress((void**)&wbh,    g_wbh);
    cudaGetSymbolAddress((void**)&wbl,    g_wbl);
    cudaGetSymbolAddress((void**)&cnt,    g_cnt);

    // idempotent device config (not an allocation)
    cudaFuncSetAttribute(gemm_bf16_kernel<F_INC, 1, 1>,
                         cudaFuncAttributeMaxDynamicSharedMemorySize, GEMM_SMEM);
    cudaFuncSetAttribute(gemm_bf16_kernel<HC, 2, 1>,
                         cudaFuncAttributeMaxDynamicSharedMemorySize, GEMM_SMEM);

    const int T = 256;
    const int edgeBlocks      = (N_EDGESC + T - 1) / T;
    const int nodeWarpBlocks  = (N_NODESC * 32 + T - 1) / T;
    const int graphWarpBlocks = (N_GRAPHSC * 32 + T - 1) / T;
    const int gemmBlocksN = (N_NODESC + 127) / 128;

    const float* u0 = uv;            const float* v0 = uv + 512;
    const float* u1 = uv + 128;      const float* v1 = uv + 640;
    const float* u2 = uv + 256;      const float* v2 = uv + 768;
    const float* u3 = uv + 384;      const float* v3 = uv + 896;

    detect_kernel<<<1, 256>>>(ei, batch);
    wsplit_kernel<<<(WS_TOTAL + T - 1) / T, T>>>(W1, gW, mW);
    uv_kernel<<<128, T>>>(gW, gasrc, gadst, mW, masrc, madst, uv);

    // h0 = leaky(x@W1+b1); fused dots -> as/ad for layer 0
    gemm_bf16_kernel<F_INC, 1, 1><<<gemmBlocksN, T, GEMM_SMEM>>>(
        x, wbh + WOFF_W1, wbl + WOFF_W1, b1, h, as_, ad_, u0, v0, N_NODESC);

    // CSR build + graph boundaries
    cudaMemsetAsync(cnt, 0, N_NODESC * sizeof(int));
    hist_kernel<<<edgeBlocks, T>>>(ei);
    scan1_kernel<<<NSB, SCB>>>();
    scan2_kernel<<<1, 256>>>();
    scan3_kernel<<<NSB, SCB>>>();
    scatter_kernel<<<edgeBlocks, T>>>(ei);
    gbounds_kernel<<<(N_GRAPHSC + 1 + T - 1) / T, T>>>(batch);

    // 3 GAT layers: aggregate raw h, then project+bias+ELU (+next dots)
    const float* us[3] = { u1, u2, u3 };
    const float* vs[3] = { v1, v2, v3 };
    for (int i = 0; i < 3; i++) {
        gat_agg_kernel<<<nodeWarpBlocks, T>>>(as_, ad_, h, hagg);
        gemm_bf16_kernel<HC, 2, 1><<<gemmBlocksN, T, GEMM_SMEM>>>(
            hagg, wbh + WOFF_G(i), wbl + WOFF_G(i), gb + i * HC, h,
            as_, ad_, us[i], vs[i], N_NODESC);
    }
    // after loop: as_ = h3 . (mW@m_asrc)  (bipartite source logits)

    pool_kernel<<<graphWarpBlocks, T>>>(h, pooled);
    adg_kernel<<<graphWarpBlocks, T>>>(pooled, v3, adg);

    final_kernel<<<graphWarpBlocks, T>>>(as_, adg, h, mW, mb, W2, b2, out);
}